// round 11
// baseline (speedup 1.0000x reference)
#include <cuda_runtime.h>
#include <cuda_fp16.h>
#include <math.h>

#define VOL   128
#define VOL2  (VOL*VOL)
#define VOL3  (VOL*VOL*VOL)
#define NB    4
#define NVOX  (NB*VOL3)
#define NV4   (NVOX/4)
#define OTY   26
#define NTY   5
#define ZSEG  7               // 140 blocks = 1 wave
#define ZLEN  19

#define HPINF2 0x7C007C00u
#define HNINF2 0xFC00FC00u
#define FULLM 0xffffffffu

// fp16 buffers (uint2 = 4 half voxels)
__device__ uint2 g_yp16[NV4];
__device__ uint2 g_tru16[NV4];
__device__ uint2 g_imgA16[NV4];
__device__ uint2 g_imgB16[NV4];
__device__ uint2 g_skel16[NV4];
__device__ float g_yp[NVOX];      // fp32 sigmoid (for tsens sum)
__device__ float g_acc[8];

__device__ __forceinline__ __half2 u2h(unsigned u) { return *reinterpret_cast<__half2*>(&u); }
__device__ __forceinline__ unsigned h2u(__half2 h) { return *reinterpret_cast<unsigned*>(&h); }

__device__ __forceinline__ uint2 hmin2u(uint2 a, uint2 b) {
    return make_uint2(h2u(__hmin2(u2h(a.x), u2h(b.x))), h2u(__hmin2(u2h(a.y), u2h(b.y))));
}
__device__ __forceinline__ uint2 hmax2u(uint2 a, uint2 b) {
    return make_uint2(h2u(__hmax2(u2h(a.x), u2h(b.x))), h2u(__hmax2(u2h(a.y), u2h(b.y))));
}
__device__ __forceinline__ uint2 hmin3u(uint2 a, uint2 b, uint2 c) { return hmin2u(hmin2u(a,b),c); }
__device__ __forceinline__ uint2 hmax3u(uint2 a, uint2 b, uint2 c) { return hmax2u(hmax2u(a,b),c); }

__device__ __forceinline__ uint2 hminS(uint2 v, int tx) {
    unsigned lb = __shfl_up_sync(FULLM, v.y, 1);
    unsigned rn = __shfl_down_sync(FULLM, v.x, 1);
    if (tx == 0)  lb = v.x << 16;
    if (tx == 31) rn = v.y >> 16;
    unsigned Lb = __byte_perm(v.x, v.y, 0x5432);
    unsigned La = __byte_perm(lb, v.x, 0x5432);
    unsigned Rb = __byte_perm(v.y, rn, 0x5432);
    uint2 L = make_uint2(La, Lb), R = make_uint2(Lb, Rb);
    return hmin3u(L, v, R);
}
__device__ __forceinline__ uint2 hmaxS(uint2 v, int tx) {
    unsigned lb = __shfl_up_sync(FULLM, v.y, 1);
    unsigned rn = __shfl_down_sync(FULLM, v.x, 1);
    if (tx == 0)  lb = v.x << 16;
    if (tx == 31) rn = v.y >> 16;
    unsigned Lb = __byte_perm(v.x, v.y, 0x5432);
    unsigned La = __byte_perm(lb, v.x, 0x5432);
    unsigned Rb = __byte_perm(v.y, rn, 0x5432);
    uint2 L = make_uint2(La, Lb), R = make_uint2(Lb, Rb);
    return hmax3u(L, v, R);
}

__device__ __forceinline__ unsigned hrelusub(unsigned a, unsigned b) {
    return h2u(__hmax2(__hsub2(u2h(a), u2h(b)), u2h(0u)));
}

__device__ __forceinline__ const uint2* pickH(int sel) {
    if (sel == 0) return g_imgA16;
    if (sel == 1) return g_imgB16;
    if (sel == 2) return g_yp16;
    return g_tru16;
}
__device__ __forceinline__ const float* pickF(int sel, const float* ext) {
    return (sel == 2) ? g_yp : ext;
}

__global__ void zero_acc_kernel() {
    if (threadIdx.x < 8) g_acc[threadIdx.x] = 0.f;
}

// ---------------------------------------------------------------------------
// prep
// ---------------------------------------------------------------------------
__global__ __launch_bounds__(256) void prep_kernel(const float* __restrict__ pred,
                                                   const float* __restrict__ tru) {
    __shared__ float sm[3][8];
    const float4* p4 = (const float4*)pred;
    const float4* t4 = (const float4*)tru;
    float4* y4 = (float4*)g_yp;
    int base = blockIdx.x * 1024 + threadIdx.x;
    float st = 0.f, sp = 0.f, stp = 0.f;
#pragma unroll
    for (int k = 0; k < 4; k++) {
        int i = base + k * 256;
        float4 t = t4[i];
        float4 x = p4[i];
        float4 p;
        p.x = 1.f / (1.f + __expf(-x.x));
        p.y = 1.f / (1.f + __expf(-x.y));
        p.z = 1.f / (1.f + __expf(-x.z));
        p.w = 1.f / (1.f + __expf(-x.w));
        y4[i] = p;
        uint2 ph, th;
        ph.x = h2u(__halves2half2(__float2half_rn(p.x), __float2half_rn(p.y)));
        ph.y = h2u(__halves2half2(__float2half_rn(p.z), __float2half_rn(p.w)));
        th.x = h2u(__halves2half2(__float2half_rn(t.x), __float2half_rn(t.y)));
        th.y = h2u(__halves2half2(__float2half_rn(t.z), __float2half_rn(t.w)));
        g_yp16[i] = ph;
        g_tru16[i] = th;
        st  += (t.x + t.y) + (t.z + t.w);
        sp  += (p.x + p.y) + (p.z + p.w);
        stp += (t.x*p.x + t.y*p.y) + (t.z*p.z + t.w*p.w);
    }
#pragma unroll
    for (int o = 16; o > 0; o >>= 1) {
        st  += __shfl_xor_sync(FULLM, st,  o);
        sp  += __shfl_xor_sync(FULLM, sp,  o);
        stp += __shfl_xor_sync(FULLM, stp, o);
    }
    int w = threadIdx.x >> 5, lane = threadIdx.x & 31;
    if (lane == 0) { sm[0][w] = st; sm[1][w] = sp; sm[2][w] = stp; }
    __syncthreads();
    if (threadIdx.x == 0) {
        float a = 0.f, b = 0.f, c = 0.f;
#pragma unroll
        for (int i = 0; i < 8; i++) { a += sm[0][i]; b += sm[1][i]; c += sm[2][i]; }
        atomicAdd(&g_acc[0], a); atomicAdd(&g_acc[1], b); atomicAdd(&g_acc[2], c);
    }
}

// ---------------------------------------------------------------------------
// init: skel16 = relu(x - dilate(erode(x)))  AND  g_imgA16 = erode(x)
// ---------------------------------------------------------------------------
__global__ __launch_bounds__(1024) void init_kernel(int inSel) {
    __shared__ uint2 As[32][32];
    __shared__ uint2 Ms[32][32];
    const uint2* __restrict__ x = pickH(inSel);

    const int tx = threadIdx.x, ty = threadIdx.y;
    const int b   = blockIdx.z;
    const int oz0 = blockIdx.y * ZLEN;
    const int oz1 = min(oz0 + ZLEN, VOL);
    const int gy  = blockIdx.x * OTY - 3 + ty;
    const bool vrow = (gy >= 0 && gy < VOL);
    const bool wr   = vrow && ty >= 3 && ty < 29;
    const int ym = ty > 0 ? ty - 1 : 0, yp = ty < 31 ? ty + 1 : 31;
    const int rowOff4 = b * (VOL3/4) + (vrow ? gy : 0) * (VOL/4) + tx;

    const uint2 P2 = make_uint2(HPINF2, HPINF2);
    const uint2 N2 = make_uint2(HNINF2, HNINF2);

    uint2 a_m1 = P2, a_m2 = P2, bxy_m1 = P2;
    uint2 m_m1 = N2, m_m2 = N2;
    uint2 e1_m1 = P2;

    int z0 = oz0 - 2;
    uint2 cur = P2;
    if (vrow && (unsigned)z0 < (unsigned)VOL)
        cur = x[z0 * (VOL2/4) + rowOff4];
    As[ty][tx] = cur;
    __syncthreads();

    for (int z = z0; z <= oz1 + 1; ++z) {
        uint2 nxt = P2;
        if (vrow && (unsigned)(z + 1) < (unsigned)VOL)
            nxt = x[(z + 1) * (VOL2/4) + rowOff4];

        uint2 up = As[ym][tx], dn = As[yp][tx];
        uint2 bxy = hmin3u(hminS(cur, tx), up, dn);
        uint2 e1 = hmin3u(a_m2, cur, bxy_m1);
        uint2 e1d = e1;
        if (!vrow || (unsigned)(z - 1) >= (unsigned)VOL) e1d = N2;
        uint2 hm = hmaxS(e1d, tx);
        Ms[ty][tx] = hm;
        __syncthreads();
        As[ty][tx] = nxt;
        uint2 mxy = hmax3u(hm, Ms[ym][tx], Ms[yp][tx]);
        int zo = z - 2;
        if (wr && zo >= oz0 && zo < oz1) {
            uint2 openv = hmax3u(m_m2, m_m1, mxy);
            uint2 s;
            s.x = hrelusub(a_m2.x, openv.x);
            s.y = hrelusub(a_m2.y, openv.y);
            int gi = zo * (VOL2/4) + rowOff4;
            g_skel16[gi] = s;
            g_imgA16[gi] = e1_m1;
        }
        __syncthreads();
        a_m2 = a_m1; a_m1 = cur; bxy_m1 = bxy;
        m_m2 = m_m1; m_m1 = mxy;
        e1_m1 = e1;
        cur = nxt;
    }
}

// ---------------------------------------------------------------------------
// iter: TWO planes per barrier. Deepened skew: mxy(w-3) from Ms ring[4],
// output zo = w-4. Sub-steps w=z (A) and w=z+1 (B) share one barrier.
// As ring[8]: write planes z+2,z+3; cross-thread reads z,z+1 (prev step);
// own reads z-2,z-1 (am2), z-4,z-3 (imgE). Ms ring[4]: write hm(z-1),hm(z);
// reads hm(z-3),hm(z-2) (prev step).
// ---------------------------------------------------------------------------
__global__ __launch_bounds__(1024) void iter_kernel(
    int inSel, int outSel, int doSum, int otherSel,
    const float* __restrict__ extOther, int accBase)
{
    extern __shared__ uint2 smemU[];   // 8*1024 (As) + 4*1024 (Ms) = 96 KB
    const int AS0 = 0, MS0 = 8192;

    const uint2* __restrict__ imgIn = pickH(inSel);
    uint2* imgOut = (outSel == 0) ? g_imgA16 : g_imgB16;
    const float* __restrict__ other = pickF(otherSel, extOther);

    const int tx = threadIdx.x, ty = threadIdx.y;
    const int b   = blockIdx.z;
    const int oz0 = blockIdx.y * ZLEN;
    const int oz1 = min(oz0 + ZLEN, VOL);
    const int gy  = blockIdx.x * OTY - 3 + ty;
    const bool vrow = (gy >= 0 && gy < VOL);
    const bool wr   = vrow && ty >= 3 && ty < 29;
    const int ym = ty > 0 ? ty - 1 : 0, yp = ty < 31 ? ty + 1 : 31;
    const int rowOff4 = b * (VOL3/4) + (vrow ? gy : 0) * (VOL/4) + tx;
    const int sIdx = ty * 32 + tx;

    const uint2 P2 = make_uint2(HPINF2, HPINF2);
    const uint2 N2 = make_uint2(HNINF2, HNINF2);

    uint2 bxy_prev = P2;                       // bxy(w-1)
    uint2 e2_m1 = P2, e2_m2 = P2, e2_m3 = P2;  // e2(w-2), e2(w-3), e2(w-4)
    uint2 m_m1 = N2, m_m2 = N2;                // mxy(w-4), mxy(w-5)
    float sumS = 0.f, sumC = 0.f;

    const int z0 = oz0 - 2;
    {
        uint2 a0 = P2, a1 = P2;
        if (vrow && (unsigned)z0 < (unsigned)VOL)
            a0 = imgIn[z0 * (VOL2/4) + rowOff4];
        if (vrow && (unsigned)(z0 + 1) < (unsigned)VOL)
            a1 = imgIn[(z0 + 1) * (VOL2/4) + rowOff4];
        smemU[AS0 + ((z0 + 16) & 7) * 1024 + sIdx] = a0;
        smemU[AS0 + ((z0 + 17) & 7) * 1024 + sIdx] = a1;
    }
#pragma unroll
    for (int s = 0; s < 4; s++) smemU[MS0 + s * 1024 + sIdx] = N2;

    uint2 p2 = P2, p3 = P2;
    if (vrow && (unsigned)(z0 + 2) < (unsigned)VOL)
        p2 = imgIn[(z0 + 2) * (VOL2/4) + rowOff4];
    if (vrow && (unsigned)(z0 + 3) < (unsigned)VOL)
        p3 = imgIn[(z0 + 3) * (VOL2/4) + rowOff4];
    __syncthreads();

    const int nstep = (oz1 - oz0 + 7) >> 1;
    for (int s = 0; s < nstep; ++s) {
        const int z = z0 + 2 * s;

        // prefetch planes z+4, z+5
        uint2 L4 = P2, L5 = P2;
        if (vrow && (unsigned)(z + 4) < (unsigned)VOL)
            L4 = imgIn[(z + 4) * (VOL2/4) + rowOff4];
        if (vrow && (unsigned)(z + 5) < (unsigned)VOL)
            L5 = imgIn[(z + 5) * (VOL2/4) + rowOff4];

        const int zoA = z - 4, zoB = z - 3;
        const bool doA = wr && zoA >= oz0 && zoA < oz1;
        const bool doB = wr && zoB >= oz0 && zoB < oz1;
        const int giA = zoA * (VOL2/4) + rowOff4;
        const int giB = zoB * (VOL2/4) + rowOff4;
        uint2 sPreA = make_uint2(0u, 0u), sPreB = make_uint2(0u, 0u);
        if (doA) sPreA = g_skel16[giA];
        if (doB) sPreB = g_skel16[giB];

        // ring writes: planes z+2, z+3
        smemU[AS0 + ((z + 18) & 7) * 1024 + sIdx] = p2;
        smemU[AS0 + ((z + 19) & 7) * 1024 + sIdx] = p3;

        // ---- sub-A (w = z) ----
        {
            const int aC  = AS0 + ((z + 16) & 7) * 1024;
            const int aM2 = AS0 + ((z + 14) & 7) * 1024;
            const int aM4 = AS0 + ((z + 12) & 7) * 1024;
            const int mW  = MS0 + ((z + 15) & 3) * 1024;  // hm(z-1)
            const int mR  = MS0 + ((z + 13) & 3) * 1024;  // hm(z-3)
            uint2 cur = smemU[aC + sIdx];
            uint2 up = smemU[aC + ym * 32 + tx], dn = smemU[aC + yp * 32 + tx];
            uint2 bxy = hmin3u(hminS(cur, tx), up, dn);
            uint2 am2 = smemU[aM2 + sIdx];
            uint2 e2 = hmin3u(am2, cur, bxy_prev);
            uint2 e2d = e2;
            if (!vrow || (unsigned)(z - 1) >= (unsigned)VOL) e2d = N2;
            uint2 hm = hmaxS(e2d, tx);
            smemU[mW + sIdx] = hm;
            uint2 mxy = hmax3u(smemU[mR + sIdx],
                               smemU[mR + ym * 32 + tx], smemU[mR + yp * 32 + tx]);
            if (doA) {
                uint2 imgE = smemU[aM4 + sIdx];
                uint2 openv = hmax3u(m_m2, m_m1, mxy);
                __half2 z2 = u2h(0u);
                __half2 d0 = __hmax2(__hsub2(u2h(imgE.x), u2h(openv.x)), z2);
                __half2 d1 = __hmax2(__hsub2(u2h(imgE.y), u2h(openv.y)), z2);
                __half2 s0 = u2h(sPreA.x), s1 = u2h(sPreA.y);
                __half2 i0 = __hmax2(__hfma2(__hneg2(s0), d0, d0), z2);
                __half2 i1 = __hmax2(__hfma2(__hneg2(s1), d1, d1), z2);
                s0 = __hadd2(s0, i0);
                s1 = __hadd2(s1, i1);
                if (!doSum) {
                    g_skel16[giA] = make_uint2(h2u(s0), h2u(s1));
                    imgOut[giA] = e2_m3;
                } else {
                    float2 f0 = __half22float2(s0), f1 = __half22float2(s1);
                    float4 o = ((const float4*)other)[giA];
                    sumS += (f0.x + f0.y) + (f1.x + f1.y);
                    sumC += (f0.x*o.x + f0.y*o.y) + (f1.x*o.z + f1.y*o.w);
                }
            }
            bxy_prev = bxy;
            e2_m3 = e2_m2; e2_m2 = e2_m1; e2_m1 = e2;
            m_m2 = m_m1; m_m1 = mxy;
        }

        // ---- sub-B (w = z+1) ----
        {
            const int aC  = AS0 + ((z + 17) & 7) * 1024;
            const int aM2 = AS0 + ((z + 15) & 7) * 1024;
            const int aM4 = AS0 + ((z + 13) & 7) * 1024;
            const int mW  = MS0 + ((z + 16) & 3) * 1024;  // hm(z)
            const int mR  = MS0 + ((z + 14) & 3) * 1024;  // hm(z-2)
            uint2 cur = smemU[aC + sIdx];
            uint2 up = smemU[aC + ym * 32 + tx], dn = smemU[aC + yp * 32 + tx];
            uint2 bxy = hmin3u(hminS(cur, tx), up, dn);
            uint2 am2 = smemU[aM2 + sIdx];
            uint2 e2 = hmin3u(am2, cur, bxy_prev);
            uint2 e2d = e2;
            if (!vrow || (unsigned)z >= (unsigned)VOL) e2d = N2;
            uint2 hm = hmaxS(e2d, tx);
            smemU[mW + sIdx] = hm;
            uint2 mxy = hmax3u(smemU[mR + sIdx],
                               smemU[mR + ym * 32 + tx], smemU[mR + yp * 32 + tx]);
            if (doB) {
                uint2 imgE = smemU[aM4 + sIdx];
                uint2 openv = hmax3u(m_m2, m_m1, mxy);
                __half2 z2 = u2h(0u);
                __half2 d0 = __hmax2(__hsub2(u2h(imgE.x), u2h(openv.x)), z2);
                __half2 d1 = __hmax2(__hsub2(u2h(imgE.y), u2h(openv.y)), z2);
                __half2 s0 = u2h(sPreB.x), s1 = u2h(sPreB.y);
                __half2 i0 = __hmax2(__hfma2(__hneg2(s0), d0, d0), z2);
                __half2 i1 = __hmax2(__hfma2(__hneg2(s1), d1, d1), z2);
                s0 = __hadd2(s0, i0);
                s1 = __hadd2(s1, i1);
                if (!doSum) {
                    g_skel16[giB] = make_uint2(h2u(s0), h2u(s1));
                    imgOut[giB] = e2_m3;
                } else {
                    float2 f0 = __half22float2(s0), f1 = __half22float2(s1);
                    float4 o = ((const float4*)other)[giB];
                    sumS += (f0.x + f0.y) + (f1.x + f1.y);
                    sumC += (f0.x*o.x + f0.y*o.y) + (f1.x*o.z + f1.y*o.w);
                }
            }
            bxy_prev = bxy;
            e2_m3 = e2_m2; e2_m2 = e2_m1; e2_m1 = e2;
            m_m2 = m_m1; m_m1 = mxy;
        }

        __syncthreads();
        p2 = L4; p3 = L5;
    }

    if (doSum) {
#pragma unroll
        for (int o = 16; o > 0; o >>= 1) {
            sumS += __shfl_xor_sync(FULLM, sumS, o);
            sumC += __shfl_xor_sync(FULLM, sumC, o);
        }
        int w = sIdx >> 5, lane = sIdx & 31;
        float* red = (float*)smemU;
        if (lane == 0) { red[w] = sumS; red[32 + w] = sumC; }
        __syncthreads();
        if (w == 0) {
            float s = red[lane], c = red[32 + lane];
#pragma unroll
            for (int o = 16; o > 0; o >>= 1) {
                s += __shfl_xor_sync(FULLM, s, o);
                c += __shfl_xor_sync(FULLM, c, o);
            }
            if (lane == 0) {
                atomicAdd(&g_acc[accBase], s);
                atomicAdd(&g_acc[accBase + 1], c);
            }
        }
    }
}

__global__ void final_kernel(float* out) {
    float st = g_acc[0], sp = g_acc[1], stp = g_acc[2];
    float skp = g_acc[3], skpt = g_acc[4], skt = g_acc[5], sktp = g_acc[6];
    float dice = 1.f - (2.f * stp + 1.f) / (st + sp + 1.f);
    float tprec = (skpt + 1.f) / (skp + 1.f);
    float tsens = (sktp + 1.f) / (skt + 1.f);
    float cl = 1.f - 2.f * (tprec * tsens) / (tprec + tsens);
    out[0] = 0.7f * dice + 0.3f * cl;
}

#define ITER_SMEM (12 * 1024 * 8)   // 96 KB

extern "C" void kernel_launch(void* const* d_in, const int* in_sizes, int n_in,
                              void* d_out, int out_size) {
    const float* pred = (const float*)d_in[0];
    const float* tru  = (const float*)d_in[1];
    float* out = (float*)d_out;

    static int smem_set = 0;
    if (!smem_set) {
        cudaFuncSetAttribute(iter_kernel, cudaFuncAttributeMaxDynamicSharedMemorySize, ITER_SMEM);
        smem_set = 1;
    }

    dim3 blk(32, 32);
    dim3 grd(NTY, ZSEG, NB);

    zero_acc_kernel<<<1, 32>>>();
    prep_kernel<<<NVOX / 4096, 256>>>(pred, tru);

    // ---- pred skeleton ----
    init_kernel<<<grd, blk>>>(2);
    for (int k = 1; k <= 16; ++k) {
        int inSel  = (k & 1) ? 0 : 1;
        int outSel = (k & 1) ? 1 : 0;
        int doSum  = (k == 16) ? 1 : 0;
        iter_kernel<<<grd, blk, ITER_SMEM>>>(inSel, outSel, doSum, 3, tru, 3);
    }

    // ---- true skeleton ----
    init_kernel<<<grd, blk>>>(3);
    for (int k = 1; k <= 16; ++k) {
        int inSel  = (k & 1) ? 0 : 1;
        int outSel = (k & 1) ? 1 : 0;
        int doSum  = (k == 16) ? 1 : 0;
        iter_kernel<<<grd, blk, ITER_SMEM>>>(inSel, outSel, doSum, 2, nullptr, 5);
    }

    final_kernel<<<1, 1>>>(out);
}

// round 12
// speedup vs baseline: 1.1075x; 1.1075x over previous
#include <cuda_runtime.h>
#include <cuda_fp16.h>
#include <math.h>

#define VOL   128
#define VOL2  (VOL*VOL)
#define VOL3  (VOL*VOL*VOL)
#define NB    4
#define NVOX  (NB*VOL3)
#define NV4   (NVOX/4)
#define OTY   26
#define NTY   5
#define ZSEG  7               // 140 blocks = 1 wave
#define ZLEN  19

#define HPINF2 0x7C007C00u
#define HNINF2 0xFC00FC00u
#define FULLM 0xffffffffu

__device__ uint2 g_yp16[NV4];
__device__ uint2 g_tru16[NV4];
__device__ uint2 g_imgA16[NV4];
__device__ uint2 g_imgB16[NV4];
__device__ uint2 g_skel16[NV4];
__device__ float g_yp[NVOX];
__device__ float g_acc[8];

__device__ __forceinline__ __half2 u2h(unsigned u) { return *reinterpret_cast<__half2*>(&u); }
__device__ __forceinline__ unsigned h2u(__half2 h) { return *reinterpret_cast<unsigned*>(&h); }

__device__ __forceinline__ uint2 hmin2u(uint2 a, uint2 b) {
    return make_uint2(h2u(__hmin2(u2h(a.x), u2h(b.x))), h2u(__hmin2(u2h(a.y), u2h(b.y))));
}
__device__ __forceinline__ uint2 hmax2u(uint2 a, uint2 b) {
    return make_uint2(h2u(__hmax2(u2h(a.x), u2h(b.x))), h2u(__hmax2(u2h(a.y), u2h(b.y))));
}
__device__ __forceinline__ uint2 hmin3u(uint2 a, uint2 b, uint2 c) { return hmin2u(hmin2u(a,b),c); }
__device__ __forceinline__ uint2 hmax3u(uint2 a, uint2 b, uint2 c) { return hmax2u(hmax2u(a,b),c); }

__device__ __forceinline__ uint2 hminS(uint2 v, int tx) {
    unsigned lb = __shfl_up_sync(FULLM, v.y, 1);
    unsigned rn = __shfl_down_sync(FULLM, v.x, 1);
    if (tx == 0)  lb = v.x << 16;
    if (tx == 31) rn = v.y >> 16;
    unsigned Lb = __byte_perm(v.x, v.y, 0x5432);
    unsigned La = __byte_perm(lb, v.x, 0x5432);
    unsigned Rb = __byte_perm(v.y, rn, 0x5432);
    uint2 L = make_uint2(La, Lb), R = make_uint2(Lb, Rb);
    return hmin3u(L, v, R);
}
__device__ __forceinline__ uint2 hmaxS(uint2 v, int tx) {
    unsigned lb = __shfl_up_sync(FULLM, v.y, 1);
    unsigned rn = __shfl_down_sync(FULLM, v.x, 1);
    if (tx == 0)  lb = v.x << 16;
    if (tx == 31) rn = v.y >> 16;
    unsigned Lb = __byte_perm(v.x, v.y, 0x5432);
    unsigned La = __byte_perm(lb, v.x, 0x5432);
    unsigned Rb = __byte_perm(v.y, rn, 0x5432);
    uint2 L = make_uint2(La, Lb), R = make_uint2(Lb, Rb);
    return hmax3u(L, v, R);
}

__device__ __forceinline__ unsigned hrelusub(unsigned a, unsigned b) {
    return h2u(__hmax2(__hsub2(u2h(a), u2h(b)), u2h(0u)));
}
// skel update: s += relu(delta - s*delta), packed half2
__device__ __forceinline__ __half2 skupd(__half2 s, __half2 d) {
    __half2 z2 = u2h(0u);
    __half2 inc = __hmax2(__hfma2(__hneg2(s), d, d), z2);
    return __hadd2(s, inc);
}

__device__ __forceinline__ const uint2* pickH(int sel) {
    if (sel == 0) return g_imgA16;
    if (sel == 1) return g_imgB16;
    if (sel == 2) return g_yp16;
    return g_tru16;
}
__device__ __forceinline__ const float* pickF(int sel, const float* ext) {
    return (sel == 2) ? g_yp : ext;
}

__global__ void zero_acc_kernel() {
    if (threadIdx.x < 8) g_acc[threadIdx.x] = 0.f;
}

// ---------------------------------------------------------------------------
// prep
// ---------------------------------------------------------------------------
__global__ __launch_bounds__(256) void prep_kernel(const float* __restrict__ pred,
                                                   const float* __restrict__ tru) {
    __shared__ float sm[3][8];
    const float4* p4 = (const float4*)pred;
    const float4* t4 = (const float4*)tru;
    float4* y4 = (float4*)g_yp;
    int base = blockIdx.x * 1024 + threadIdx.x;
    float st = 0.f, sp = 0.f, stp = 0.f;
#pragma unroll
    for (int k = 0; k < 4; k++) {
        int i = base + k * 256;
        float4 t = t4[i];
        float4 x = p4[i];
        float4 p;
        p.x = 1.f / (1.f + __expf(-x.x));
        p.y = 1.f / (1.f + __expf(-x.y));
        p.z = 1.f / (1.f + __expf(-x.z));
        p.w = 1.f / (1.f + __expf(-x.w));
        y4[i] = p;
        uint2 ph, th;
        ph.x = h2u(__halves2half2(__float2half_rn(p.x), __float2half_rn(p.y)));
        ph.y = h2u(__halves2half2(__float2half_rn(p.z), __float2half_rn(p.w)));
        th.x = h2u(__halves2half2(__float2half_rn(t.x), __float2half_rn(t.y)));
        th.y = h2u(__halves2half2(__float2half_rn(t.z), __float2half_rn(t.w)));
        g_yp16[i] = ph;
        g_tru16[i] = th;
        st  += (t.x + t.y) + (t.z + t.w);
        sp  += (p.x + p.y) + (p.z + p.w);
        stp += (t.x*p.x + t.y*p.y) + (t.z*p.z + t.w*p.w);
    }
#pragma unroll
    for (int o = 16; o > 0; o >>= 1) {
        st  += __shfl_xor_sync(FULLM, st,  o);
        sp  += __shfl_xor_sync(FULLM, sp,  o);
        stp += __shfl_xor_sync(FULLM, stp, o);
    }
    int w = threadIdx.x >> 5, lane = threadIdx.x & 31;
    if (lane == 0) { sm[0][w] = st; sm[1][w] = sp; sm[2][w] = stp; }
    __syncthreads();
    if (threadIdx.x == 0) {
        float a = 0.f, b = 0.f, c = 0.f;
#pragma unroll
        for (int i = 0; i < 8; i++) { a += sm[0][i]; b += sm[1][i]; c += sm[2][i]; }
        atomicAdd(&g_acc[0], a); atomicAdd(&g_acc[1], b); atomicAdd(&g_acc[2], c);
    }
}

// ---------------------------------------------------------------------------
// init: skel16 = relu(x - dilate(erode(x)))  AND  g_imgA16 = erode(x)
// ---------------------------------------------------------------------------
__global__ __launch_bounds__(1024) void init_kernel(int inSel) {
    __shared__ uint2 As[32][32];
    __shared__ uint2 Ms[32][32];
    const uint2* __restrict__ x = pickH(inSel);

    const int tx = threadIdx.x, ty = threadIdx.y;
    const int b   = blockIdx.z;
    const int oz0 = blockIdx.y * ZLEN;
    const int oz1 = min(oz0 + ZLEN, VOL);
    const int gy  = blockIdx.x * OTY - 3 + ty;
    const bool vrow = (gy >= 0 && gy < VOL);
    const bool wr   = vrow && ty >= 3 && ty < 29;
    const int ym = ty > 0 ? ty - 1 : 0, yp = ty < 31 ? ty + 1 : 31;
    const int rowOff4 = b * (VOL3/4) + (vrow ? gy : 0) * (VOL/4) + tx;

    const uint2 P2 = make_uint2(HPINF2, HPINF2);
    const uint2 N2 = make_uint2(HNINF2, HNINF2);

    uint2 a_m1 = P2, a_m2 = P2, bxy_m1 = P2;
    uint2 m_m1 = N2, m_m2 = N2;
    uint2 e1_m1 = P2;

    int z0 = oz0 - 2;
    uint2 cur = P2;
    if (vrow && (unsigned)z0 < (unsigned)VOL)
        cur = x[z0 * (VOL2/4) + rowOff4];
    As[ty][tx] = cur;
    __syncthreads();

    for (int z = z0; z <= oz1 + 1; ++z) {
        uint2 nxt = P2;
        if (vrow && (unsigned)(z + 1) < (unsigned)VOL)
            nxt = x[(z + 1) * (VOL2/4) + rowOff4];

        uint2 up = As[ym][tx], dn = As[yp][tx];
        uint2 bxy = hmin3u(hminS(cur, tx), up, dn);
        uint2 e1 = hmin3u(a_m2, cur, bxy_m1);
        uint2 e1d = e1;
        if (!vrow || (unsigned)(z - 1) >= (unsigned)VOL) e1d = N2;
        uint2 hm = hmaxS(e1d, tx);
        Ms[ty][tx] = hm;
        __syncthreads();
        As[ty][tx] = nxt;
        uint2 mxy = hmax3u(hm, Ms[ym][tx], Ms[yp][tx]);
        int zo = z - 2;
        if (wr && zo >= oz0 && zo < oz1) {
            uint2 openv = hmax3u(m_m2, m_m1, mxy);
            uint2 s;
            s.x = hrelusub(a_m2.x, openv.x);
            s.y = hrelusub(a_m2.y, openv.y);
            int gi = zo * (VOL2/4) + rowOff4;
            g_skel16[gi] = s;
            g_imgA16[gi] = e1_m1;
        }
        __syncthreads();
        a_m2 = a_m1; a_m1 = cur; bxy_m1 = bxy;
        m_m2 = m_m1; m_m1 = mxy;
        e1_m1 = e1;
        cur = nxt;
    }
}

// ---------------------------------------------------------------------------
// iter2: TWO skeleton iterations per launch. Input imgE_k.
//   e1(w) = erode(imgE_k)(w) = imgE_{k+1};  e2(w) = erode(e1)(w) = imgE_{k+2}
//   delta_k(w)   = relu(imgE_k(w)   - dilate(e1)(w))
//   delta_k+1(w) = relu(e1(w)       - dilate(e2)(w))
//   skel <- upd(upd(skel, delta_k), delta_k+1);  write e2 as next image.
// Rings: As[8] (img planes), Es[4] (e1 planes), Ms1[2]/Ms2[2] (row-hmax).
// One barrier per plane. Output zo = z-4.
// ---------------------------------------------------------------------------
__global__ __launch_bounds__(1024) void iter2_kernel(
    int inSel, int outSel, int doSum, int otherSel,
    const float* __restrict__ extOther, int accBase)
{
    extern __shared__ uint2 smemU[];   // 8+4+2+2 = 16 slots * 8KB = 128 KB
    const int AS0 = 0, ES0 = 8192, MS1 = 12288, MS2 = 14336;

    const uint2* __restrict__ imgIn = pickH(inSel);
    uint2* imgOut = (outSel == 0) ? g_imgA16 : g_imgB16;
    const float* __restrict__ other = pickF(otherSel, extOther);

    const int tx = threadIdx.x, ty = threadIdx.y;
    const int b   = blockIdx.z;
    const int oz0 = blockIdx.y * ZLEN;
    const int oz1 = min(oz0 + ZLEN, VOL);
    const int gy  = blockIdx.x * OTY - 3 + ty;
    const bool vrow = (gy >= 0 && gy < VOL);
    const bool wr   = vrow && ty >= 3 && ty < 29;
    const int ym = ty > 0 ? ty - 1 : 0, yp = ty < 31 ? ty + 1 : 31;
    const int rowOff4 = b * (VOL3/4) + (vrow ? gy : 0) * (VOL/4) + tx;
    const int sIdx = ty * 32 + tx;

    const uint2 P2 = make_uint2(HPINF2, HPINF2);
    const uint2 N2 = make_uint2(HNINF2, HNINF2);

    uint2 bxyA_prev = P2;
    uint2 hm1_m1 = N2, hm2_m1 = N2;
    uint2 m1_m1 = N2, m1_m2 = N2;
    uint2 m2_m1 = N2, m2_m2 = N2;
    uint2 e2_m1 = P2, e2_m2 = P2;
    uint2 d1_m1 = make_uint2(0u, 0u);
    float sumS = 0.f, sumC = 0.f;

    const int z0 = oz0 - 4;
    // prefill rings
#pragma unroll
    for (int s = 0; s < 8; s++) smemU[AS0 + s * 1024 + sIdx] = P2;
#pragma unroll
    for (int s = 0; s < 4; s++) smemU[ES0 + s * 1024 + sIdx] = P2;
    smemU[MS1 + sIdx] = N2; smemU[MS1 + 1024 + sIdx] = N2;
    smemU[MS2 + sIdx] = N2; smemU[MS2 + 1024 + sIdx] = N2;
    {
        uint2 a0 = P2;
        if (vrow && (unsigned)z0 < (unsigned)VOL)
            a0 = imgIn[z0 * (VOL2/4) + rowOff4];
        smemU[AS0 + ((z0 + 16) & 7) * 1024 + sIdx] = a0;
    }
    uint2 pW = P2;
    if (vrow && (unsigned)(z0 + 1) < (unsigned)VOL)
        pW = imgIn[(z0 + 1) * (VOL2/4) + rowOff4];
    __syncthreads();

    for (int z = z0; z <= oz1 + 3; ++z) {
        // prefetch A(z+2)
        uint2 L = P2;
        if (vrow && (unsigned)(z + 2) < (unsigned)VOL)
            L = imgIn[(z + 2) * (VOL2/4) + rowOff4];

        const int zo = z - 4;
        const bool doOut = wr && zo >= oz0 && zo < oz1;
        const int gi = zo * (VOL2/4) + rowOff4;
        uint2 sPre = make_uint2(0u, 0u);
        if (doOut) sPre = g_skel16[gi];

        smemU[AS0 + ((z + 17) & 7) * 1024 + sIdx] = pW;      // A(z+1)

        // ---- stage 1: e1(z-1) = erode(A)(z-1); hm1(z-1) ----
        const int aC = AS0 + ((z + 16) & 7) * 1024;          // A(z)
        uint2 cur = smemU[aC + sIdx];
        uint2 upA = smemU[aC + ym * 32 + tx], dnA = smemU[aC + yp * 32 + tx];
        uint2 bxyA = hmin3u(hminS(cur, tx), upA, dnA);
        uint2 am2 = smemU[AS0 + ((z + 14) & 7) * 1024 + sIdx]; // A(z-2)
        uint2 e1 = hmin3u(am2, cur, bxyA_prev);
        bool v1 = vrow && (unsigned)(z - 1) < (unsigned)VOL;
        uint2 e1p = v1 ? e1 : P2;
        uint2 e1d = v1 ? e1 : N2;
        smemU[ES0 + ((z + 15) & 3) * 1024 + sIdx] = e1p;     // e1(z-1)
        uint2 hm1 = hmaxS(e1d, tx);
        smemU[MS1 + ((z + 15) & 1) * 1024 + sIdx] = hm1;     // hm1(z-1)

        // ---- stage 2: e2(z-2) = erode(e1)(z-2); hm2(z-2) ----
        const int eC = ES0 + ((z + 14) & 3) * 1024;          // e1(z-2)
        uint2 esOwn = smemU[eC + sIdx];
        uint2 upE = smemU[eC + ym * 32 + tx], dnE = smemU[eC + yp * 32 + tx];
        uint2 bxyE = hmin3u(hminS(esOwn, tx), upE, dnE);
        uint2 em3 = smemU[ES0 + ((z + 13) & 3) * 1024 + sIdx]; // e1(z-3)
        uint2 e2 = hmin3u(em3, e1p, bxyE);
        bool v2 = vrow && (unsigned)(z - 2) < (unsigned)VOL;
        uint2 e2d = v2 ? e2 : N2;
        uint2 hm2 = hmaxS(e2d, tx);
        smemU[MS2 + ((z + 14) & 1) * 1024 + sIdx] = hm2;     // hm2(z-2)

        // ---- in-plane 3x3 maxes ----
        const int m1R = MS1 + ((z + 14) & 1) * 1024;         // hm1(z-2)
        uint2 mxy1 = hmax3u(hm1_m1, smemU[m1R + ym * 32 + tx], smemU[m1R + yp * 32 + tx]);
        const int m2R = MS2 + ((z + 13) & 1) * 1024;         // hm2(z-3)
        uint2 mxy2 = hmax3u(hm2_m1, smemU[m2R + ym * 32 + tx], smemU[m2R + yp * 32 + tx]);

        // ---- delta_k at zo1 = z-3 ----
        uint2 open1 = hmax3u(m1_m2, m1_m1, mxy1);            // dilate(e1) at z-3
        uint2 aZo1 = smemU[AS0 + ((z + 13) & 7) * 1024 + sIdx]; // A(z-3)
        uint2 d1;
        d1.x = hrelusub(aZo1.x, open1.x);
        d1.y = hrelusub(aZo1.y, open1.y);

        // ---- output at zo = z-4 ----
        if (doOut) {
            uint2 open2 = hmax3u(m2_m2, m2_m1, mxy2);        // dilate(e2) at z-4
            uint2 e1Zo = smemU[ES0 + ((z + 12) & 3) * 1024 + sIdx]; // e1(z-4)
            uint2 d2;
            d2.x = hrelusub(e1Zo.x, open2.x);
            d2.y = hrelusub(e1Zo.y, open2.y);
            __half2 s0 = u2h(sPre.x), s1 = u2h(sPre.y);
            s0 = skupd(s0, u2h(d1_m1.x));
            s1 = skupd(s1, u2h(d1_m1.y));
            s0 = skupd(s0, u2h(d2.x));
            s1 = skupd(s1, u2h(d2.y));
            if (!doSum) {
                g_skel16[gi] = make_uint2(h2u(s0), h2u(s1));
                imgOut[gi] = e2_m2;                          // imgE_{k+2}(zo)
            } else {
                float2 f0 = __half22float2(s0), f1 = __half22float2(s1);
                float4 o = ((const float4*)other)[gi];
                sumS += (f0.x + f0.y) + (f1.x + f1.y);
                sumC += (f0.x*o.x + f0.y*o.y) + (f1.x*o.z + f1.y*o.w);
            }
        }

        __syncthreads();

        bxyA_prev = bxyA;
        hm1_m1 = hm1; hm2_m1 = hm2;
        m1_m2 = m1_m1; m1_m1 = mxy1;
        m2_m2 = m2_m1; m2_m1 = mxy2;
        e2_m2 = e2_m1; e2_m1 = e2;
        d1_m1 = d1;
        pW = L;
    }

    if (doSum) {
#pragma unroll
        for (int o = 16; o > 0; o >>= 1) {
            sumS += __shfl_xor_sync(FULLM, sumS, o);
            sumC += __shfl_xor_sync(FULLM, sumC, o);
        }
        int w = sIdx >> 5, lane = sIdx & 31;
        float* red = (float*)smemU;
        if (lane == 0) { red[w] = sumS; red[32 + w] = sumC; }
        __syncthreads();
        if (w == 0) {
            float s = red[lane], c = red[32 + lane];
#pragma unroll
            for (int o = 16; o > 0; o >>= 1) {
                s += __shfl_xor_sync(FULLM, s, o);
                c += __shfl_xor_sync(FULLM, c, o);
            }
            if (lane == 0) {
                atomicAdd(&g_acc[accBase], s);
                atomicAdd(&g_acc[accBase + 1], c);
            }
        }
    }
}

__global__ void final_kernel(float* out) {
    float st = g_acc[0], sp = g_acc[1], stp = g_acc[2];
    float skp = g_acc[3], skpt = g_acc[4], skt = g_acc[5], sktp = g_acc[6];
    float dice = 1.f - (2.f * stp + 1.f) / (st + sp + 1.f);
    float tprec = (skpt + 1.f) / (skp + 1.f);
    float tsens = (sktp + 1.f) / (skt + 1.f);
    float cl = 1.f - 2.f * (tprec * tsens) / (tprec + tsens);
    out[0] = 0.7f * dice + 0.3f * cl;
}

#define ITER_SMEM (16 * 1024 * 8)   // 128 KB

extern "C" void kernel_launch(void* const* d_in, const int* in_sizes, int n_in,
                              void* d_out, int out_size) {
    const float* pred = (const float*)d_in[0];
    const float* tru  = (const float*)d_in[1];
    float* out = (float*)d_out;

    static int smem_set = 0;
    if (!smem_set) {
        cudaFuncSetAttribute(iter2_kernel, cudaFuncAttributeMaxDynamicSharedMemorySize, ITER_SMEM);
        smem_set = 1;
    }

    dim3 blk(32, 32);
    dim3 grd(NTY, ZSEG, NB);

    zero_acc_kernel<<<1, 32>>>();
    prep_kernel<<<NVOX / 4096, 256>>>(pred, tru);

    // ---- pred skeleton: init does iter-0 skel + imgA16 = erode(yp16);
    //      8 double-iter launches cover iterations 1..16 ----
    init_kernel<<<grd, blk>>>(2);
    for (int j = 1; j <= 8; ++j) {
        int inSel  = (j & 1) ? 0 : 1;
        int outSel = (j & 1) ? 1 : 0;
        int doSum  = (j == 8) ? 1 : 0;
        iter2_kernel<<<grd, blk, ITER_SMEM>>>(inSel, outSel, doSum, 3, tru, 3);
    }

    // ---- true skeleton ----
    init_kernel<<<grd, blk>>>(3);
    for (int j = 1; j <= 8; ++j) {
        int inSel  = (j & 1) ? 0 : 1;
        int outSel = (j & 1) ? 1 : 0;
        int doSum  = (j == 8) ? 1 : 0;
        iter2_kernel<<<grd, blk, ITER_SMEM>>>(inSel, outSel, doSum, 2, nullptr, 5);
    }

    final_kernel<<<1, 1>>>(out);
}